// round 1
// baseline (speedup 1.0000x reference)
#include <cuda_runtime.h>

#define LATENTS 128
#define HIDDEN  256
#define TM      32       // rows per CTA
#define NTHR    256
#define TSTEPS  100
#define NROWS   4096

// tanh(x) = 1 - 2/(exp(2x)+1); exact at +/-inf via __expf saturation.
__device__ __forceinline__ float fast_tanh(float x) {
    float e = __expf(2.0f * x);
    return 1.0f - __fdividef(2.0f, e + 1.0f);
}

__global__ __launch_bounds__(NTHR, 1)
void ode_rk4_kernel(const float* __restrict__ fp,
                    const float* __restrict__ ts,
                    const float* __restrict__ W1,
                    const float* __restrict__ b1,
                    const float* __restrict__ W2,
                    const float* __restrict__ b2,
                    float* __restrict__ out)
{
    extern __shared__ float sm[];
    float* W1s = sm;                        // [128][256] fp32, 128 KB
    float* Ye  = sm + LATENTS * HIDDEN;     // [TM][128] current eval point
    float* Zs  = Ye + TM * LATENTS;         // [TM][256] tanh activations

    const int tid  = threadIdx.x;
    const int tc   = tid & 31;              // lane
    const int tr   = tid >> 5;              // warp (0..7) -> row group
    const int row0 = blockIdx.x * TM;

    // Stage W1 into smem once (coalesced float4).
    for (int i = tid; i < LATENTS * HIDDEN / 4; i += NTHR)
        ((float4*)W1s)[i] = ((const float4*)W1)[i];

    // Biases into registers for this thread's output columns.
    float rb1[8], rb2[4];
    #pragma unroll
    for (int i = 0; i < 8; i++) rb1[i] = b1[tc + 32 * i];     // GEMM1 cols: tc + 32i
    {
        float4 bv = *(const float4*)&b2[tc * 4];              // GEMM2 cols: 4tc + i
        rb2[0] = bv.x; rb2[1] = bv.y; rb2[2] = bv.z; rb2[3] = bv.w;
    }

    // Load initial state into registers (this thread's 4 rows x 4 cols),
    // seed Ye, and emit t=0 output.
    float yb[4][4];
    #pragma unroll
    for (int q = 0; q < 4; q++) {
        int r = tr * 4 + q;
        float4 v = *(const float4*)&fp[(size_t)(row0 + r) * LATENTS + tc * 4];
        yb[q][0] = v.x; yb[q][1] = v.y; yb[q][2] = v.z; yb[q][3] = v.w;
        *(float4*)&out[((size_t)(row0 + r) * TSTEPS) * LATENTS + tc * 4] = v;
        *(float4*)&Ye[r * LATENTS + tc * 4] = v;
    }
    __syncthreads();

    float acc[4][4];

    for (int t = 0; t < TSTEPS - 1; t++) {
        float t0   = __ldg(&ts[t]);
        float dt   = __ldg(&ts[t + 1]) - t0;
        float half = 0.5f * dt;

        #pragma unroll 1
        for (int s = 0; s < 4; s++) {
            // ---- GEMM1: h[TM][256] = Ye @ W1 + b1 (W1 from smem) ----
            float h[4][8];
            #pragma unroll
            for (int q = 0; q < 4; q++)
                #pragma unroll
                for (int i = 0; i < 8; i++) h[q][i] = rb1[i];

            #pragma unroll 4
            for (int k = 0; k < LATENTS; k++) {
                float w[8];
                #pragma unroll
                for (int i = 0; i < 8; i++) w[i] = W1s[k * HIDDEN + tc + 32 * i];
                float yv[4];
                #pragma unroll
                for (int q = 0; q < 4; q++) yv[q] = Ye[(tr * 4 + q) * LATENTS + k];
                #pragma unroll
                for (int q = 0; q < 4; q++)
                    #pragma unroll
                    for (int i = 0; i < 8; i++)
                        h[q][i] = fmaf(yv[q], w[i], h[q][i]);
            }

            // ---- tanh -> Zs (lane-contiguous STS, conflict-free) ----
            #pragma unroll
            for (int q = 0; q < 4; q++) {
                int r = tr * 4 + q;
                #pragma unroll
                for (int i = 0; i < 8; i++)
                    Zs[r * HIDDEN + tc + 32 * i] = fast_tanh(h[q][i]);
            }
            __syncthreads();

            // ---- GEMM2: o[TM][128] = Zs @ W2 + b2 (W2 from global/L2) ----
            float o[4][4];
            #pragma unroll
            for (int q = 0; q < 4; q++)
                #pragma unroll
                for (int i = 0; i < 4; i++) o[q][i] = rb2[i];

            #pragma unroll 4
            for (int k = 0; k < HIDDEN; k++) {
                float4 wv = __ldg((const float4*)&W2[k * LATENTS + tc * 4]);
                float zv[4];
                #pragma unroll
                for (int q = 0; q < 4; q++) zv[q] = Zs[(tr * 4 + q) * HIDDEN + k];
                #pragma unroll
                for (int q = 0; q < 4; q++) {
                    o[q][0] = fmaf(zv[q], wv.x, o[q][0]);
                    o[q][1] = fmaf(zv[q], wv.y, o[q][1]);
                    o[q][2] = fmaf(zv[q], wv.z, o[q][2]);
                    o[q][3] = fmaf(zv[q], wv.w, o[q][3]);
                }
            }

            // ---- RK4 stage combine ----
            if (s == 0) {
                #pragma unroll
                for (int q = 0; q < 4; q++)
                    #pragma unroll
                    for (int i = 0; i < 4; i++) acc[q][i] = o[q][i];
            } else {
                float cw = (s == 3) ? 1.0f : 2.0f;
                #pragma unroll
                for (int q = 0; q < 4; q++)
                    #pragma unroll
                    for (int i = 0; i < 4; i++)
                        acc[q][i] = fmaf(cw, o[q][i], acc[q][i]);
            }

            if (s < 3) {
                float ew = (s < 2) ? half : dt;  // k2,k3 eval at +dt/2; k4 at +dt
                #pragma unroll
                for (int q = 0; q < 4; q++) {
                    int r = tr * 4 + q;
                    float4 v;
                    v.x = fmaf(ew, o[q][0], yb[q][0]);
                    v.y = fmaf(ew, o[q][1], yb[q][1]);
                    v.z = fmaf(ew, o[q][2], yb[q][2]);
                    v.w = fmaf(ew, o[q][3], yb[q][3]);
                    *(float4*)&Ye[r * LATENTS + tc * 4] = v;
                }
            } else {
                float c6 = dt * (1.0f / 6.0f);
                #pragma unroll
                for (int q = 0; q < 4; q++) {
                    int r = tr * 4 + q;
                    #pragma unroll
                    for (int i = 0; i < 4; i++)
                        yb[q][i] = fmaf(c6, acc[q][i], yb[q][i]);
                    float4 v;
                    v.x = yb[q][0]; v.y = yb[q][1]; v.z = yb[q][2]; v.w = yb[q][3];
                    *(float4*)&Ye[r * LATENTS + tc * 4] = v;
                    *(float4*)&out[((size_t)(row0 + r) * TSTEPS + (t + 1)) * LATENTS + tc * 4] = v;
                }
            }
            __syncthreads();
        }
    }
}

extern "C" void kernel_launch(void* const* d_in, const int* in_sizes, int n_in,
                              void* d_out, int out_size) {
    const float* fp = (const float*)d_in[0];  // first_point (4,1024,128)
    const float* ts = (const float*)d_in[1];  // time_steps (100)
    const float* W1 = (const float*)d_in[2];  // (128,256)
    const float* b1 = (const float*)d_in[3];  // (256)
    const float* W2 = (const float*)d_in[4];  // (256,128)
    const float* b2 = (const float*)d_in[5];  // (128)
    float* out = (float*)d_out;               // (4,1024,100,128)

    size_t smem = (size_t)(LATENTS * HIDDEN + TM * LATENTS + TM * HIDDEN) * sizeof(float);
    cudaFuncSetAttribute(ode_rk4_kernel,
                         cudaFuncAttributeMaxDynamicSharedMemorySize, (int)smem);
    ode_rk4_kernel<<<NROWS / TM, NTHR, smem>>>(fp, ts, W1, b1, W2, b2, out);
}

// round 2
// speedup vs baseline: 1.0664x; 1.0664x over previous
#include <cuda_runtime.h>

#define LATENTS 128
#define HIDDEN  256
#define TM      32
#define NTHR    512
#define TSTEPS  100
#define NROWS   4096

typedef unsigned long long ULL;

// dual fp32 FMA: d.lo = a.lo*b.lo+c.lo ; d.hi = a.hi*b.hi+c.hi
__device__ __forceinline__ ULL ffma2(ULL a, ULL b, ULL c) {
    ULL d;
    asm("fma.rn.f32x2 %0, %1, %2, %3;" : "=l"(d) : "l"(a), "l"(b), "l"(c));
    return d;
}
__device__ __forceinline__ ULL pack2(float x) {
    ULL d;
    asm("mov.b64 %0, {%1, %1};" : "=l"(d) : "f"(x));
    return d;
}
__device__ __forceinline__ ULL packab(float a, float b) {
    ULL d;
    asm("mov.b64 %0, {%1, %2};" : "=l"(d) : "f"(a), "f"(b));
    return d;
}
__device__ __forceinline__ void unpack2(ULL v, float& lo, float& hi) {
    asm("mov.b64 {%0, %1}, %2;" : "=f"(lo), "=f"(hi) : "l"(v));
}

__device__ __forceinline__ float fast_tanh(float x) {
    float e = __expf(2.0f * x);
    return 1.0f - __fdividef(2.0f, e + 1.0f);
}

// smem layout (bytes):
//   W1s : [0,          131072)   float  [128][256]
//   Yes : [131072,     147456)   float  [32][128]
//   Zd  : [147456,     212992)   ULL    [32][256]  duplicated (z,z) pairs
//   W2t : [212992,     229376)   float  [32][128]  k-tile of W2
#define SM_BYTES 229376

__global__ __launch_bounds__(NTHR, 1)
void ode_rk4_kernel(const float* __restrict__ fp,
                    const float* __restrict__ ts,
                    const float* __restrict__ W1,
                    const float* __restrict__ b1,
                    const float* __restrict__ W2,
                    const float* __restrict__ b2,
                    float* __restrict__ out)
{
    extern __shared__ char smraw[];
    float* W1s = (float*)smraw;
    float* Yes = (float*)(smraw + 131072);
    ULL*   Zd  = (ULL*)  (smraw + 147456);
    float* W2t = (float*)(smraw + 212992);

    const int tid  = threadIdx.x;
    const int tc   = tid & 31;
    const int w    = tid >> 5;          // warp 0..15
    const int r0   = 2 * w;             // this warp's two rows
    const int r1   = r0 + 1;
    const int row0 = blockIdx.x * TM;

    // Stage W1 into smem (coalesced float4).
    #pragma unroll
    for (int i = tid; i < LATENTS * HIDDEN / 4; i += NTHR)
        ((float4*)W1s)[i] = ((const float4*)W1)[i];

    // Bias pairs. GEMM1 cols: pairs (2tc+64p, 2tc+64p+1). GEMM2 cols: 4tc..4tc+3.
    ULL rb1[4], rb2[2];
    #pragma unroll
    for (int p = 0; p < 4; p++) rb1[p] = *(const ULL*)&b1[2 * tc + 64 * p];
    rb2[0] = *(const ULL*)&b2[4 * tc];
    rb2[1] = *(const ULL*)&b2[4 * tc + 2];

    // Initial state: 2 rows x 4 cols (4tc..4tc+3) per thread.
    float yb[2][4];
    #pragma unroll
    for (int q = 0; q < 2; q++) {
        int r = r0 + q;
        float4 v = *(const float4*)&fp[(size_t)(row0 + r) * LATENTS + 4 * tc];
        yb[q][0] = v.x; yb[q][1] = v.y; yb[q][2] = v.z; yb[q][3] = v.w;
        *(float4*)&Yes[r * LATENTS + 4 * tc] = v;
        *(float4*)&out[((size_t)(row0 + r) * TSTEPS) * LATENTS + 4 * tc] = v;
    }
    __syncthreads();

    float acc[2][4];

    for (int t = 0; t < TSTEPS - 1; t++) {
        float dt   = __ldg(&ts[t + 1]) - __ldg(&ts[t]);
        float half = 0.5f * dt;

        #pragma unroll 1
        for (int s = 0; s < 4; s++) {
            // -------- prefetch W2 tile 0 into regs (hidden under GEMM1) ----
            float4 nxtA = ((const float4*)W2)[tid];
            float4 nxtB = ((const float4*)W2)[tid + NTHR];

            // -------- GEMM1: [2 rows] x [8 cols as 4 pairs], W1 from smem --
            ULL h0[4], h1[4];
            #pragma unroll
            for (int p = 0; p < 4; p++) { h0[p] = rb1[p]; h1[p] = rb1[p]; }

            #pragma unroll 1
            for (int k = 0; k < LATENTS; k += 4) {
                float4 ya4 = *(const float4*)&Yes[r0 * LATENTS + k];
                float4 yb4 = *(const float4*)&Yes[r1 * LATENTS + k];
                const float* ya = &ya4.x;
                const float* yB = &yb4.x;
                #pragma unroll
                for (int kk = 0; kk < 4; kk++) {
                    ULL pa = pack2(ya[kk]);
                    ULL pb = pack2(yB[kk]);
                    const float* wrow = &W1s[(k + kk) * HIDDEN + 2 * tc];
                    #pragma unroll
                    for (int p = 0; p < 4; p++) {
                        ULL wv = *(const ULL*)&wrow[64 * p];
                        h0[p] = ffma2(pa, wv, h0[p]);
                        h1[p] = ffma2(pb, wv, h1[p]);
                    }
                }
            }

            // -------- tanh -> Zd (duplicated pairs, warp-private rows) -----
            #pragma unroll
            for (int p = 0; p < 4; p++) {
                int c = 2 * tc + 64 * p;
                float a, b;
                unpack2(h0[p], a, b);
                Zd[r0 * HIDDEN + c]     = pack2(fast_tanh(a));
                Zd[r0 * HIDDEN + c + 1] = pack2(fast_tanh(b));
                unpack2(h1[p], a, b);
                Zd[r1 * HIDDEN + c]     = pack2(fast_tanh(a));
                Zd[r1 * HIDDEN + c + 1] = pack2(fast_tanh(b));
            }
            __syncwarp();

            // -------- GEMM2: [2 rows] x [4 cols as 2 pairs], tiled W2 ------
            ULL o0[2], o1[2];
            o0[0] = rb2[0]; o0[1] = rb2[1];
            o1[0] = rb2[0]; o1[1] = rb2[1];

            #pragma unroll 1
            for (int kt = 0; kt < 8; kt++) {
                __syncthreads();                       // prev tile consumed
                ((float4*)W2t)[tid]        = nxtA;
                ((float4*)W2t)[tid + NTHR] = nxtB;
                __syncthreads();                       // tile ready
                if (kt < 7) {
                    const float4* src = (const float4*)(W2 + (kt + 1) * 32 * LATENTS);
                    nxtA = src[tid];
                    nxtB = src[tid + NTHR];
                }
                const ULL* zr0 = &Zd[r0 * HIDDEN + kt * 32];
                const ULL* zr1 = &Zd[r1 * HIDDEN + kt * 32];
                #pragma unroll 2
                for (int kk = 0; kk < 32; kk += 2) {
                    ulonglong2 z0 = *(const ulonglong2*)&zr0[kk];
                    ulonglong2 z1 = *(const ulonglong2*)&zr1[kk];
                    ulonglong2 wa = *(const ulonglong2*)&W2t[kk * LATENTS + 4 * tc];
                    ulonglong2 wb = *(const ulonglong2*)&W2t[(kk + 1) * LATENTS + 4 * tc];
                    o0[0] = ffma2(z0.x, wa.x, o0[0]);
                    o0[1] = ffma2(z0.x, wa.y, o0[1]);
                    o1[0] = ffma2(z1.x, wa.x, o1[0]);
                    o1[1] = ffma2(z1.x, wa.y, o1[1]);
                    o0[0] = ffma2(z0.y, wb.x, o0[0]);
                    o0[1] = ffma2(z0.y, wb.y, o0[1]);
                    o1[0] = ffma2(z1.y, wb.x, o1[0]);
                    o1[1] = ffma2(z1.y, wb.y, o1[1]);
                }
            }

            // -------- RK4 stage combine --------
            float of[2][4];
            unpack2(o0[0], of[0][0], of[0][1]);
            unpack2(o0[1], of[0][2], of[0][3]);
            unpack2(o1[0], of[1][0], of[1][1]);
            unpack2(o1[1], of[1][2], of[1][3]);

            if (s == 0) {
                #pragma unroll
                for (int q = 0; q < 2; q++)
                    #pragma unroll
                    for (int i = 0; i < 4; i++) acc[q][i] = of[q][i];
            } else {
                float cw = (s == 3) ? 1.0f : 2.0f;
                #pragma unroll
                for (int q = 0; q < 2; q++)
                    #pragma unroll
                    for (int i = 0; i < 4; i++)
                        acc[q][i] = fmaf(cw, of[q][i], acc[q][i]);
            }

            if (s < 3) {
                float ew = (s < 2) ? half : dt;
                #pragma unroll
                for (int q = 0; q < 2; q++) {
                    float4 v;
                    v.x = fmaf(ew, of[q][0], yb[q][0]);
                    v.y = fmaf(ew, of[q][1], yb[q][1]);
                    v.z = fmaf(ew, of[q][2], yb[q][2]);
                    v.w = fmaf(ew, of[q][3], yb[q][3]);
                    *(float4*)&Yes[(r0 + q) * LATENTS + 4 * tc] = v;
                }
            } else {
                float c6 = dt * (1.0f / 6.0f);
                #pragma unroll
                for (int q = 0; q < 2; q++) {
                    #pragma unroll
                    for (int i = 0; i < 4; i++)
                        yb[q][i] = fmaf(c6, acc[q][i], yb[q][i]);
                    float4 v;
                    v.x = yb[q][0]; v.y = yb[q][1]; v.z = yb[q][2]; v.w = yb[q][3];
                    *(float4*)&Yes[(r0 + q) * LATENTS + 4 * tc] = v;
                    *(float4*)&out[((size_t)(row0 + r0 + q) * TSTEPS + (t + 1)) * LATENTS + 4 * tc] = v;
                }
            }
            __syncwarp();
        }
    }
}

extern "C" void kernel_launch(void* const* d_in, const int* in_sizes, int n_in,
                              void* d_out, int out_size) {
    const float* fp = (const float*)d_in[0];
    const float* ts = (const float*)d_in[1];
    const float* W1 = (const float*)d_in[2];
    const float* b1 = (const float*)d_in[3];
    const float* W2 = (const float*)d_in[4];
    const float* b2 = (const float*)d_in[5];
    float* out = (float*)d_out;

    cudaFuncSetAttribute(ode_rk4_kernel,
                         cudaFuncAttributeMaxDynamicSharedMemorySize, SM_BYTES);
    ode_rk4_kernel<<<NROWS / TM, NTHR, SM_BYTES>>>(fp, ts, W1, b1, W2, b2, out);
}

// round 3
// speedup vs baseline: 1.5691x; 1.4713x over previous
#include <cuda_runtime.h>

#define LATENTS 128
#define HIDDEN  256
#define TM      32
#define NTHR    512
#define TSTEPS  100
#define NROWS   4096

typedef unsigned long long ULL;

__device__ __forceinline__ ULL ffma2(ULL a, ULL b, ULL c) {
    ULL d; asm("fma.rn.f32x2 %0, %1, %2, %3;" : "=l"(d) : "l"(a), "l"(b), "l"(c)); return d;
}
__device__ __forceinline__ ULL pack2(float x) {
    ULL d; asm("mov.b64 %0, {%1, %1};" : "=l"(d) : "f"(x)); return d;
}
__device__ __forceinline__ ULL packab(float a, float b) {
    ULL d; asm("mov.b64 %0, {%1, %2};" : "=l"(d) : "f"(a), "f"(b)); return d;
}
__device__ __forceinline__ void unpack2(ULL v, float& lo, float& hi) {
    asm("mov.b64 {%0, %1}, %2;" : "=f"(lo), "=f"(hi) : "l"(v));
}
__device__ __forceinline__ float fast_tanh(float x) {
    float e = __expf(2.0f * x);
    return 1.0f - __fdividef(2.0f, e + 1.0f);
}

// smem (bytes): W1s [0,131072) fp32[128][256]
//               Yp  [131072,147456) ULL[16][128]  row-pairs of state
//               Zp  [147456,180224) ULL[16][256]  row-pairs of tanh acts
//               W2t [180224,212992) fp32[2][32][128] double-buffered tiles
#define SM_BYTES 212992

__global__ __launch_bounds__(NTHR, 1)
void ode_rk4_kernel(const float* __restrict__ fp,
                    const float* __restrict__ ts,
                    const float* __restrict__ W1,
                    const float* __restrict__ b1,
                    const float* __restrict__ W2,
                    const float* __restrict__ b2,
                    float* __restrict__ out)
{
    extern __shared__ char smraw[];
    float* W1s = (float*)smraw;
    ULL*   Yp  = (ULL*)(smraw + 131072);
    ULL*   Zp  = (ULL*)(smraw + 147456);
    float* W2t = (float*)(smraw + 180224);

    const int tid = threadIdx.x;
    const int tc  = tid & 31;
    const int w   = tid >> 5;
    const int wr  = w >> 2;          // GEMM1 row group: pairs 4wr..4wr+3
    const int wc  = w & 3;           // GEMM1 col block: 64wc
    const int rg  = w >> 1;          // GEMM2 (w<8): pairs 4rg..4rg+3
    const int wc2 = w & 1;           // GEMM2 col block: 64wc2
    const bool compute_w = (w < 8);
    const int row0 = blockIdx.x * TM;

    // Stage W1 (coalesced float4).
    for (int i = tid; i < LATENTS * HIDDEN / 4; i += NTHR)
        ((float4*)W1s)[i] = ((const float4*)W1)[i];

    // t=0 output, fully coalesced.
    for (int i = tid; i < TM * LATENTS / 4; i += NTHR) {
        int r = i >> 5, c4 = i & 31;
        float4 v = ((const float4*)(fp + (size_t)(row0 + r) * LATENTS))[c4];
        ((float4*)(out + (size_t)(row0 + r) * TSTEPS * LATENTS))[c4] = v;
    }

    const ULL rb1lo = pack2(b1[64 * wc + 2 * tc]);
    const ULL rb1hi = pack2(b1[64 * wc + 2 * tc + 1]);

    ULL yb[4][2], acc[4][2], rb2[2];
    const int cb = 64 * wc2 + 2 * tc;
    if (compute_w) {
        rb2[0] = pack2(b2[cb]);
        rb2[1] = pack2(b2[cb + 1]);
        #pragma unroll
        for (int p = 0; p < 4; p++) {
            int r = row0 + 8 * rg + 2 * p;
            yb[p][0] = packab(fp[(size_t)r * LATENTS + cb],     fp[(size_t)(r + 1) * LATENTS + cb]);
            yb[p][1] = packab(fp[(size_t)r * LATENTS + cb + 1], fp[(size_t)(r + 1) * LATENTS + cb + 1]);
            ulonglong2 yy; yy.x = yb[p][0]; yy.y = yb[p][1];
            *(ulonglong2*)&Yp[(4 * rg + p) * LATENTS + cb] = yy;
        }
    }
    __syncthreads();

    for (int t = 0; t < TSTEPS - 1; t++) {
        float dt   = __ldg(&ts[t + 1]) - __ldg(&ts[t]);
        float half = 0.5f * dt;

        #pragma unroll 1
        for (int s = 0; s < 4; s++) {
            // Copy warps: prefetch W2 tile 0 during GEMM1.
            float4 tw[4];
            const int li = (w - 8) * 32 + tc;
            if (!compute_w) {
                const float4* src = (const float4*)W2;
                #pragma unroll
                for (int j = 0; j < 4; j++) tw[j] = __ldg(&src[li + 256 * j]);
            }

            // ---------------- GEMM1 (all 16 warps, row-pair) ----------------
            ULL h[4][2];
            #pragma unroll
            for (int p = 0; p < 4; p++) { h[p][0] = rb1lo; h[p][1] = rb1hi; }

            {
                const float* w1c = &W1s[64 * wc + 2 * tc];
                const ULL*   yp0 = &Yp[(4 * wr + 0) * LATENTS];
                const ULL*   yp1 = &Yp[(4 * wr + 1) * LATENTS];
                const ULL*   yp2 = &Yp[(4 * wr + 2) * LATENTS];
                const ULL*   yp3 = &Yp[(4 * wr + 3) * LATENTS];
                #pragma unroll 2
                for (int k0 = 0; k0 < LATENTS; k0 += 2) {
                    ulonglong2 a0 = *(const ulonglong2*)&yp0[k0];
                    ulonglong2 a1 = *(const ulonglong2*)&yp1[k0];
                    ulonglong2 a2 = *(const ulonglong2*)&yp2[k0];
                    ulonglong2 a3 = *(const ulonglong2*)&yp3[k0];
                    ULL wv0 = *(const ULL*)&w1c[(k0    ) * HIDDEN];
                    ULL wv1 = *(const ULL*)&w1c[(k0 + 1) * HIDDEN];
                    float wl, wh;
                    unpack2(wv0, wl, wh);
                    { ULL bl = pack2(wl), bh = pack2(wh);
                      h[0][0] = ffma2(a0.x, bl, h[0][0]); h[0][1] = ffma2(a0.x, bh, h[0][1]);
                      h[1][0] = ffma2(a1.x, bl, h[1][0]); h[1][1] = ffma2(a1.x, bh, h[1][1]);
                      h[2][0] = ffma2(a2.x, bl, h[2][0]); h[2][1] = ffma2(a2.x, bh, h[2][1]);
                      h[3][0] = ffma2(a3.x, bl, h[3][0]); h[3][1] = ffma2(a3.x, bh, h[3][1]); }
                    unpack2(wv1, wl, wh);
                    { ULL bl = pack2(wl), bh = pack2(wh);
                      h[0][0] = ffma2(a0.y, bl, h[0][0]); h[0][1] = ffma2(a0.y, bh, h[0][1]);
                      h[1][0] = ffma2(a1.y, bl, h[1][0]); h[1][1] = ffma2(a1.y, bh, h[1][1]);
                      h[2][0] = ffma2(a2.y, bl, h[2][0]); h[2][1] = ffma2(a2.y, bh, h[2][1]);
                      h[3][0] = ffma2(a3.y, bl, h[3][0]); h[3][1] = ffma2(a3.y, bh, h[3][1]); }
                }
            }

            // tanh -> Zp (dense STS.128, conflict-free).
            #pragma unroll
            for (int p = 0; p < 4; p++) {
                float x0, x1, x2, x3;
                unpack2(h[p][0], x0, x1);
                unpack2(h[p][1], x2, x3);
                ulonglong2 zz;
                zz.x = packab(fast_tanh(x0), fast_tanh(x1));
                zz.y = packab(fast_tanh(x2), fast_tanh(x3));
                *(ulonglong2*)&Zp[(4 * wr + p) * HIDDEN + 64 * wc + 2 * tc] = zz;
            }
            __syncthreads();

            // ---------------- GEMM2 (warps 0-7 compute, 8-15 copy) ----------
            ULL o[4][2];
            if (compute_w) {
                #pragma unroll
                for (int p = 0; p < 4; p++) { o[p][0] = rb2[0]; o[p][1] = rb2[1]; }
            } else {
                float4* dst = (float4*)W2t;
                #pragma unroll
                for (int j = 0; j < 4; j++) dst[li + 256 * j] = tw[j];
            }
            __syncthreads();

            #pragma unroll 1
            for (int kt = 0; kt < 8; kt++) {
                if (!compute_w) {
                    if (kt < 7) {
                        const float4* src = (const float4*)(W2 + (kt + 1) * 32 * LATENTS);
                        #pragma unroll
                        for (int j = 0; j < 4; j++) tw[j] = __ldg(&src[li + 256 * j]);
                        float4* dst = (float4*)(W2t + ((kt + 1) & 1) * 4096);
                        #pragma unroll
                        for (int j = 0; j < 4; j++) dst[li + 256 * j] = tw[j];
                    }
                } else {
                    const float* Wt = W2t + (kt & 1) * 4096 + cb;
                    const ULL* zb0 = &Zp[(4 * rg + 0) * HIDDEN + kt * 32];
                    const ULL* zb1 = &Zp[(4 * rg + 1) * HIDDEN + kt * 32];
                    const ULL* zb2 = &Zp[(4 * rg + 2) * HIDDEN + kt * 32];
                    const ULL* zb3 = &Zp[(4 * rg + 3) * HIDDEN + kt * 32];
                    #pragma unroll 4
                    for (int kk0 = 0; kk0 < 32; kk0 += 2) {
                        ulonglong2 z0 = *(const ulonglong2*)&zb0[kk0];
                        ulonglong2 z1 = *(const ulonglong2*)&zb1[kk0];
                        ulonglong2 z2 = *(const ulonglong2*)&zb2[kk0];
                        ulonglong2 z3 = *(const ulonglong2*)&zb3[kk0];
                        ULL wv0 = *(const ULL*)&Wt[(kk0    ) * LATENTS];
                        ULL wv1 = *(const ULL*)&Wt[(kk0 + 1) * LATENTS];
                        float wl, wh;
                        unpack2(wv0, wl, wh);
                        { ULL bl = pack2(wl), bh = pack2(wh);
                          o[0][0] = ffma2(z0.x, bl, o[0][0]); o[0][1] = ffma2(z0.x, bh, o[0][1]);
                          o[1][0] = ffma2(z1.x, bl, o[1][0]); o[1][1] = ffma2(z1.x, bh, o[1][1]);
                          o[2][0] = ffma2(z2.x, bl, o[2][0]); o[2][1] = ffma2(z2.x, bh, o[2][1]);
                          o[3][0] = ffma2(z3.x, bl, o[3][0]); o[3][1] = ffma2(z3.x, bh, o[3][1]); }
                        unpack2(wv1, wl, wh);
                        { ULL bl = pack2(wl), bh = pack2(wh);
                          o[0][0] = ffma2(z0.y, bl, o[0][0]); o[0][1] = ffma2(z0.y, bh, o[0][1]);
                          o[1][0] = ffma2(z1.y, bl, o[1][0]); o[1][1] = ffma2(z1.y, bh, o[1][1]);
                          o[2][0] = ffma2(z2.y, bl, o[2][0]); o[2][1] = ffma2(z2.y, bh, o[2][1]);
                          o[3][0] = ffma2(z3.y, bl, o[3][0]); o[3][1] = ffma2(z3.y, bh, o[3][1]); }
                    }
                }
                __syncthreads();
            }

            // ---------------- RK4 epilogue (packed, warps 0-7) --------------
            if (compute_w) {
                if (s == 0) {
                    #pragma unroll
                    for (int p = 0; p < 4; p++) { acc[p][0] = o[p][0]; acc[p][1] = o[p][1]; }
                } else {
                    ULL cwv = pack2((s == 3) ? 1.0f : 2.0f);
                    #pragma unroll
                    for (int p = 0; p < 4; p++) {
                        acc[p][0] = ffma2(cwv, o[p][0], acc[p][0]);
                        acc[p][1] = ffma2(cwv, o[p][1], acc[p][1]);
                    }
                }
                if (s < 3) {
                    ULL ewv = pack2((s < 2) ? half : dt);
                    #pragma unroll
                    for (int p = 0; p < 4; p++) {
                        ulonglong2 yy;
                        yy.x = ffma2(ewv, o[p][0], yb[p][0]);
                        yy.y = ffma2(ewv, o[p][1], yb[p][1]);
                        *(ulonglong2*)&Yp[(4 * rg + p) * LATENTS + cb] = yy;
                    }
                } else {
                    ULL c6 = pack2(dt * (1.0f / 6.0f));
                    #pragma unroll
                    for (int p = 0; p < 4; p++) {
                        yb[p][0] = ffma2(c6, acc[p][0], yb[p][0]);
                        yb[p][1] = ffma2(c6, acc[p][1], yb[p][1]);
                        ulonglong2 yy; yy.x = yb[p][0]; yy.y = yb[p][1];
                        *(ulonglong2*)&Yp[(4 * rg + p) * LATENTS + cb] = yy;
                        int r = row0 + 8 * rg + 2 * p;
                        float lo, hi;
                        size_t base0 = ((size_t)r * TSTEPS + (t + 1)) * LATENTS + cb;
                        size_t base1 = ((size_t)(r + 1) * TSTEPS + (t + 1)) * LATENTS + cb;
                        unpack2(yb[p][0], lo, hi);
                        out[base0] = lo;     out[base1] = hi;
                        unpack2(yb[p][1], lo, hi);
                        out[base0 + 1] = lo; out[base1 + 1] = hi;
                    }
                }
            }
            __syncthreads();
        }
    }
}

extern "C" void kernel_launch(void* const* d_in, const int* in_sizes, int n_in,
                              void* d_out, int out_size) {
    const float* fp = (const float*)d_in[0];
    const float* ts = (const float*)d_in[1];
    const float* W1 = (const float*)d_in[2];
    const float* b1 = (const float*)d_in[3];
    const float* W2 = (const float*)d_in[4];
    const float* b2 = (const float*)d_in[5];
    float* out = (float*)d_out;

    cudaFuncSetAttribute(ode_rk4_kernel,
                         cudaFuncAttributeMaxDynamicSharedMemorySize, SM_BYTES);
    ode_rk4_kernel<<<NROWS / TM, NTHR, SM_BYTES>>>(fp, ts, W1, b1, W2, b2, out);
}